// round 15
// baseline (speedup 1.0000x reference)
#include <cuda_runtime.h>
#include <cuda_bf16.h>
#include <cstdint>
#include <cstddef>

// ===================== scratch (no allocations allowed) =====================
#define MAX_EDGES 2000000
#define MAX_NODES 100000
#define SLACK 128

__device__ __align__(128) __nv_bfloat16 g_rpH[(size_t)(MAX_EDGES + SLACK) * 16];
__device__ __align__(128) __nv_bfloat16 g_rpL[(size_t)(MAX_EDGES + SLACK) * 16];
__device__ __align__(128) __nv_bfloat16 g_Xh[(size_t)(MAX_EDGES + SLACK) * 160];
__device__ __align__(128) __nv_bfloat16 g_Xl[(size_t)(MAX_EDGES + SLACK) * 160];
__device__ __align__(128) __nv_bfloat16 g_Yh[(size_t)(MAX_EDGES + SLACK) * 160];
__device__ __align__(128) __nv_bfloat16 g_Yl[(size_t)(MAX_EDGES + SLACK) * 160];
__device__ float g_eprime[(size_t)MAX_NODES * 64];
__device__ __align__(128) __nv_bfloat16 g_wstage[262144];

// ===================== low-level helpers =====================================
__device__ __forceinline__ uint32_t smem_u32(const void* p) {
    uint32_t a;
    asm("{ .reg .u64 t; cvta.to.shared.u64 t, %1; cvt.u32.u64 %0, t; }" : "=r"(a) : "l"(p));
    return a;
}
__device__ __forceinline__ void cpa16(uint32_t dst, const void* src) {
    asm volatile("cp.async.cg.shared.global [%0], [%1], 16;" :: "r"(dst), "l"(src));
}
#define CP_COMMIT() asm volatile("cp.async.commit_group;" ::: "memory")
#define CP_WAIT0()  asm volatile("cp.async.wait_group 0;" ::: "memory")
#define CP_WAIT1()  asm volatile("cp.async.wait_group 1;" ::: "memory")

__device__ __forceinline__ void mma_bf16(float* c, const uint32_t* a, uint32_t b0, uint32_t b1) {
    asm volatile(
        "mma.sync.aligned.m16n8k16.row.col.f32.bf16.bf16.f32 "
        "{%0,%1,%2,%3}, {%4,%5,%6,%7}, {%8,%9}, {%0,%1,%2,%3};"
        : "+f"(c[0]), "+f"(c[1]), "+f"(c[2]), "+f"(c[3])
        : "r"(a[0]), "r"(a[1]), "r"(a[2]), "r"(a[3]), "r"(b0), "r"(b1));
}
__device__ __forceinline__ void red2(float* gp, float v0, float v1) {
    asm volatile("red.global.add.v2.f32 [%0], {%1, %2};" :: "l"(gp), "f"(v0), "f"(v1) : "memory");
}
__device__ __forceinline__ void split2(float v0, float v1, uint32_t& hi, uint32_t& lo) {
    __nv_bfloat16 h0 = __float2bfloat16(v0), h1 = __float2bfloat16(v1);
    __nv_bfloat16 l0 = __float2bfloat16(v0 - __bfloat162float(h0));
    __nv_bfloat16 l1 = __float2bfloat16(v1 - __bfloat162float(h1));
    hi = (uint32_t)__bfloat16_as_ushort(h0) | ((uint32_t)__bfloat16_as_ushort(h1) << 16);
    lo = (uint32_t)__bfloat16_as_ushort(l0) | ((uint32_t)__bfloat16_as_ushort(l1) << 16);
}

// pack acc -> hi/lo uint4 with relu + col150=1
__device__ __forceinline__ void pack_epi(const float* a0, const float* a1, int slice, int tg,
                                         uint4& hv, uint4& lv) {
    uint32_t ph[4], pl[4];
#pragma unroll
    for (int nh = 0; nh < 2; nh++) {
        const float* a = nh ? a1 : a0;
        float v0 = fmaxf(a[0], 0.f);
        float v1 = fmaxf(a[1], 0.f);
        float v2 = fmaxf(a[2], 0.f);
        float v3 = fmaxf(a[3], 0.f);
        int gc = slice * 16 + nh * 8 + tg * 2;
        if (gc == 150)     { v0 = 1.f; v2 = 1.f; }
        if (gc + 1 == 150) { v1 = 1.f; v3 = 1.f; }
        split2(v0, v1, ph[nh*2],   pl[nh*2]);
        split2(v2, v3, ph[nh*2+1], pl[nh*2+1]);
    }
    hv = make_uint4(ph[0], ph[1], ph[2], ph[3]);
    lv = make_uint4(pl[0], pl[1], pl[2], pl[3]);
}

// ===================== merged weight prep ====================================
struct PrepCfg {
    const float* W; const float* b;
    int din, dout, KD, WSTR, brow, off;
};
struct PrepPack { PrepCfg c[5]; };

__global__ void prep_all(PrepPack p, __nv_bfloat16* __restrict__ wst, int total)
{
    int idx = blockIdx.x * blockDim.x + threadIdx.x;
    if (idx >= total) return;
#pragma unroll
    for (int L = 0; L < 5; L++) {
        int tot = p.c[L].KD * p.c[L].WSTR;
        if (idx < tot) {
            int k = idx / p.c[L].WSTR, n = idx - k * p.c[L].WSTR;
            float v = 0.f;
            if (n < p.c[L].dout) {
                if (k < p.c[L].din) v = p.c[L].W[(size_t)k * p.c[L].dout + n];
                else if (k == p.c[L].brow) v = p.c[L].b[n];
            }
            __nv_bfloat16 h = __float2bfloat16(v);
            __nv_bfloat16 l = __float2bfloat16(v - __bfloat162float(h));
            wst[p.c[L].off + idx] = h;
            wst[p.c[L].off + tot + idx] = l;
            return;
        }
        idx -= tot;
    }
}

// B fragment gather from weight image (ushort layout [KD][WSTR], hi then lo)
__device__ __forceinline__ void wfrag(const ushort* WH, const ushort* WL, int WSTR,
                                      int k0, int slice, int g, int tg,
                                      uint32_t* bh, uint32_t* bl) {
#pragma unroll
    for (int nh = 0; nh < 2; nh++)
#pragma unroll
        for (int r = 0; r < 2; r++) {
            int k = k0 * 16 + tg * 2 + r * 8;
            int n = slice * 16 + nh * 8 + g;
            bh[nh*2+r] = (uint32_t)WH[k*WSTR+n] | ((uint32_t)WH[(k+1)*WSTR+n] << 16);
            bl[nh*2+r] = (uint32_t)WL[k*WSTR+n] | ((uint32_t)WL[(k+1)*WSTR+n] << 16);
        }
}

// ===================== gather ================================================
__global__ void gather_kernel(const float* __restrict__ x,
                              const float* __restrict__ ofx,
                              const int* __restrict__ src,
                              const int* __restrict__ tgt,
                              const float* __restrict__ t,
                              __nv_bfloat16* __restrict__ oh,
                              __nv_bfloat16* __restrict__ ol, int M)
{
    int e = blockIdx.x * blockDim.x + threadIdx.x;
    if (e >= M) return;
    int s = src[e], g = tgt[e];
    float v[16];
    float4 xs = *(const float4*)(x + (size_t)4 * s);
    float2 os = *(const float2*)(ofx + (size_t)2 * s);
    float4 xt = *(const float4*)(x + (size_t)4 * g);
    float2 ot = *(const float2*)(ofx + (size_t)2 * g);
    v[0]=xs.x; v[1]=xs.y; v[2]=xs.z; v[3]=xs.w; v[4]=os.x; v[5]=os.y;
    v[6]=xt.x; v[7]=xt.y; v[8]=xt.z; v[9]=xt.w; v[10]=ot.x; v[11]=ot.y;
    v[12]=t[0]; v[13]=1.0f; v[14]=0.f; v[15]=0.f;
    uint32_t wh[8], wl[8];
#pragma unroll
    for (int i = 0; i < 8; i++) split2(v[2*i], v[2*i+1], wh[i], wl[i]);
    uint4* ph = (uint4*)(oh + (size_t)e * 16);
    uint4* pl = (uint4*)(ol + (size_t)e * 16);
    ph[0] = make_uint4(wh[0], wh[1], wh[2], wh[3]);
    ph[1] = make_uint4(wh[4], wh[5], wh[6], wh[7]);
    pl[0] = make_uint4(wl[0], wl[1], wl[2], wl[3]);
    pl[1] = make_uint4(wl[4], wl[5], wl[6], wl[7]);
}

__global__ void zero_kernel(float* __restrict__ p, int n)
{
    int i = blockIdx.x * blockDim.x + threadIdx.x;
    if (i < n) p[i] = 0.f;
}

// ===================== pair1: L0+L1 fused, 2-D unit ownership ================
// warp = (mh = wid&1 -> subs {2mh,2mh+1}, np = wid>>1 -> slices {2np,2np+1})
// shared unit: slice 8+(np&1), sub 2mh+(np>>1)  (sub within own half).
__global__ __launch_bounds__(256, 1)
void pair1_kernel(const __nv_bfloat16* __restrict__ rpH,
                  const __nv_bfloat16* __restrict__ rpL,
                  const __nv_bfloat16* __restrict__ w1img,   // [16][168] hi,lo
                  const __nv_bfloat16* __restrict__ w2img,   // [160][168] hi,lo
                  __nv_bfloat16* __restrict__ outH,
                  __nv_bfloat16* __restrict__ outL,
                  int M)
{
    constexpr int WSTR = 168;
    extern __shared__ unsigned char smem[];
    uint4* INT = (uint4*)smem;                       // 2 bufs x 2560 uint4
    uint4* RB2 = (uint4*)(smem + 81920);             // [10 sl][5 k0][32] hi(1600), lo(+1600)
    uint4* SB2 = (uint4*)(smem + 133120);            // [2 sl][5 k0][32] hi(320), lo(+320)

    const int tid = threadIdx.x, wid = tid >> 5, lane = tid & 31;
    const int g = lane >> 2, tg = lane & 3;
    const int mh = wid & 1, np = wid >> 1;
    const int sl0 = np * 2, sb0 = mh * 2;
    const int ssl = 8 + (np & 1);                    // shared slice
    const int shi = np >> 1;                         // shared sub = sb0 + shi

    const ushort* W1H = (const ushort*)w1img;
    const ushort* W1L = W1H + 16 * WSTR;
    const ushort* W2H = (const ushort*)w2img;
    const ushort* W2L = W2H + 160 * WSTR;

    // B1 regs: slices sl0, sl0+1, ssl
    uint32_t b1h[3][4], b1l[3][4];
    wfrag(W1H, W1L, WSTR, 0, sl0,     g, tg, b1h[0], b1l[0]);
    wfrag(W1H, W1L, WSTR, 0, sl0 + 1, g, tg, b1h[1], b1l[1]);
    wfrag(W1H, W1L, WSTR, 0, ssl,     g, tg, b1h[2], b1l[2]);

    // B2 regs: slices sl0, sl0+1, k0 0..4
    uint32_t pbh[2][5][4], pbl[2][5][4];
#pragma unroll
    for (int s2 = 0; s2 < 2; s2++)
#pragma unroll
        for (int k0 = 0; k0 < 5; k0++)
            wfrag(W2H, W2L, WSTR, k0, sl0 + s2, g, tg, pbh[s2][k0], pbl[s2][k0]);

    // RB2: all 10 slices, k0 5..9 (warp w builds slices w, w+8)
    for (int s = wid; s < 10; s += 8) {
        for (int k0 = 5; k0 < 10; k0++) {
            uint32_t bh[4], bl[4];
            wfrag(W2H, W2L, WSTR, k0, s, g, tg, bh, bl);
            RB2[(s*5 + k0 - 5)*32 + lane]        = make_uint4(bh[0], bh[1], bh[2], bh[3]);
            RB2[1600 + (s*5 + k0 - 5)*32 + lane] = make_uint4(bl[0], bl[1], bl[2], bl[3]);
        }
    }
    // SB2: slices 8,9 k0 0..4 (warps 0,1)
    if (wid < 2) {
        int slice = 8 + wid;
        for (int k0 = 0; k0 < 5; k0++) {
            uint32_t bh[4], bl[4];
            wfrag(W2H, W2L, WSTR, k0, slice, g, tg, bh, bl);
            SB2[(wid*5 + k0)*32 + lane]       = make_uint4(bh[0], bh[1], bh[2], bh[3]);
            SB2[320 + (wid*5 + k0)*32 + lane] = make_uint4(bl[0], bl[1], bl[2], bl[3]);
        }
    }
    __syncthreads();

    const int ntiles = (M + 63) >> 6;

    uint32_t pAH[2][4], pAL[2][4];   // A frags for own 2 subs
    auto loadA = [&](int tile) {
        const int row0 = tile << 6;
#pragma unroll
        for (int si = 0; si < 2; si++) {
            const int sub = sb0 + si;
            int r0 = row0 + sub * 16 + g;
            int r1 = r0 + 8;
            if (r0 > M - 1) r0 = M - 1;
            if (r1 > M - 1) r1 = M - 1;
            const __nv_bfloat16* h0p = rpH + (size_t)r0 * 16 + tg * 2;
            const __nv_bfloat16* h1p = rpH + (size_t)r1 * 16 + tg * 2;
            const __nv_bfloat16* l0p = rpL + (size_t)r0 * 16 + tg * 2;
            const __nv_bfloat16* l1p = rpL + (size_t)r1 * 16 + tg * 2;
            pAH[si][0] = *(const uint32_t*)h0p;
            pAH[si][1] = *(const uint32_t*)h1p;
            pAH[si][2] = *(const uint32_t*)(h0p + 8);
            pAH[si][3] = *(const uint32_t*)(h1p + 8);
            pAL[si][0] = *(const uint32_t*)l0p;
            pAL[si][1] = *(const uint32_t*)l1p;
            pAL[si][2] = *(const uint32_t*)(l0p + 8);
            pAL[si][3] = *(const uint32_t*)(l1p + 8);
        }
    };

    auto g1 = [&](int buf) {
        uint4* ih = INT + buf * 2560;
#pragma unroll
        for (int si = 0; si < 2; si++) {
            const int sub = sb0 + si;
            float acc[2][2][4] = {};
#pragma unroll
            for (int s2 = 0; s2 < 2; s2++) {
                mma_bf16(acc[s2][0], pAH[si], b1h[s2][0], b1h[s2][1]);
                mma_bf16(acc[s2][0], pAH[si], b1l[s2][0], b1l[s2][1]);
                mma_bf16(acc[s2][0], pAL[si], b1h[s2][0], b1h[s2][1]);
                mma_bf16(acc[s2][1], pAH[si], b1h[s2][2], b1h[s2][3]);
                mma_bf16(acc[s2][1], pAH[si], b1l[s2][2], b1l[s2][3]);
                mma_bf16(acc[s2][1], pAL[si], b1h[s2][2], b1h[s2][3]);
            }
#pragma unroll
            for (int s2 = 0; s2 < 2; s2++) {
                uint4 hv, lv;
                pack_epi(acc[s2][0], acc[s2][1], sl0 + s2, tg, hv, lv);
                ih[((sl0+s2)*4 + sub)*32 + lane]        = hv;
                ih[1280 + ((sl0+s2)*4 + sub)*32 + lane] = lv;
            }
        }
        {   // shared unit
            float acc[2][4] = {};
            mma_bf16(acc[0], pAH[shi], b1h[2][0], b1h[2][1]);
            mma_bf16(acc[0], pAH[shi], b1l[2][0], b1l[2][1]);
            mma_bf16(acc[0], pAL[shi], b1h[2][0], b1h[2][1]);
            mma_bf16(acc[1], pAH[shi], b1h[2][2], b1h[2][3]);
            mma_bf16(acc[1], pAH[shi], b1l[2][2], b1l[2][3]);
            mma_bf16(acc[1], pAL[shi], b1h[2][2], b1h[2][3]);
            uint4 hv, lv;
            pack_epi(acc[0], acc[1], ssl, tg, hv, lv);
            ih[(ssl*4 + sb0 + shi)*32 + lane]        = hv;
            ih[1280 + (ssl*4 + sb0 + shi)*32 + lane] = lv;
        }
    };

    auto g2 = [&](int tile, int buf) {
        const uint4* ip = INT + buf * 2560;
        float am[2][2][2][4] = {};     // [si][s2][nh]
        float as[2][4] = {};           // shared
#pragma unroll
        for (int k0 = 0; k0 < 10; k0++) {
            uint32_t aH[2][4], aL[2][4];
#pragma unroll
            for (int si = 0; si < 2; si++) {
                uint4 a4 = ip[(k0*4 + sb0 + si)*32 + lane];
                uint4 b4 = ip[1280 + (k0*4 + sb0 + si)*32 + lane];
                aH[si][0]=a4.x; aH[si][1]=a4.y; aH[si][2]=a4.z; aH[si][3]=a4.w;
                aL[si][0]=b4.x; aL[si][1]=b4.y; aL[si][2]=b4.z; aL[si][3]=b4.w;
            }
#pragma unroll
            for (int s2 = 0; s2 < 2; s2++) {
                uint32_t bh[4], bl[4];
                if (k0 < 5) {
#pragma unroll
                    for (int q = 0; q < 4; q++) { bh[q] = pbh[s2][k0][q]; bl[q] = pbl[s2][k0][q]; }
                } else {
                    uint4 h4 = RB2[((sl0+s2)*5 + k0 - 5)*32 + lane];
                    uint4 l4 = RB2[1600 + ((sl0+s2)*5 + k0 - 5)*32 + lane];
                    bh[0]=h4.x; bh[1]=h4.y; bh[2]=h4.z; bh[3]=h4.w;
                    bl[0]=l4.x; bl[1]=l4.y; bl[2]=l4.z; bl[3]=l4.w;
                }
#pragma unroll
                for (int si = 0; si < 2; si++) {
                    mma_bf16(am[si][s2][0], aH[si], bh[0], bh[1]);
                    mma_bf16(am[si][s2][0], aH[si], bl[0], bl[1]);
                    mma_bf16(am[si][s2][0], aL[si], bh[0], bh[1]);
                    mma_bf16(am[si][s2][1], aH[si], bh[2], bh[3]);
                    mma_bf16(am[si][s2][1], aH[si], bl[2], bl[3]);
                    mma_bf16(am[si][s2][1], aL[si], bh[2], bh[3]);
                }
            }
            {   // shared unit: B slice ssl
                uint4 h4, l4;
                if (k0 < 5) {
                    h4 = SB2[((ssl-8)*5 + k0)*32 + lane];
                    l4 = SB2[320 + ((ssl-8)*5 + k0)*32 + lane];
                } else {
                    h4 = RB2[(ssl*5 + k0 - 5)*32 + lane];
                    l4 = RB2[1600 + (ssl*5 + k0 - 5)*32 + lane];
                }
                mma_bf16(as[0], aH[shi], h4.x, h4.y);
                mma_bf16(as[0], aH[shi], l4.x, l4.y);
                mma_bf16(as[0], aL[shi], h4.x, h4.y);
                mma_bf16(as[1], aH[shi], h4.z, h4.w);
                mma_bf16(as[1], aH[shi], l4.z, l4.w);
                mma_bf16(as[1], aL[shi], h4.z, h4.w);
            }
        }
        uint4* oh = (uint4*)outH;
        uint4* ol = (uint4*)outL;
#pragma unroll
        for (int si = 0; si < 2; si++)
#pragma unroll
            for (int s2 = 0; s2 < 2; s2++) {
                uint4 hv, lv;
                pack_epi(am[si][s2][0], am[si][s2][1], sl0 + s2, tg, hv, lv);
                size_t base = ((size_t)tile * 40 + (sl0+s2)*4 + sb0 + si) * 32 + lane;
                oh[base] = hv;
                ol[base] = lv;
            }
        {
            uint4 hv, lv;
            pack_epi(as[0], as[1], ssl, tg, hv, lv);
            size_t base = ((size_t)tile * 40 + ssl*4 + sb0 + shi) * 32 + lane;
            oh[base] = hv;
            ol[base] = lv;
        }
    };

    int t = blockIdx.x;
    if (t < ntiles) { loadA(t); g1(0); }
    int i = 0;
    for (; t < ntiles; t += gridDim.x, i++) {
        int nxt = t + gridDim.x;
        if (nxt < ntiles) loadA(nxt);
        __syncthreads();
        g2(t, i & 1);
        if (nxt < ntiles) g1((i + 1) & 1);
    }
}

// ===================== pair2: L2+L3 ==========================================
// G1: 2-D unit ownership, k0-outer, B from c1 cache.
// G2: warp=slice, k0-outer all 5 units fused (shared-A reuse), B regs full k.
__global__ __launch_bounds__(256, 1)
void pair2_kernel(const __nv_bfloat16* __restrict__ inH,
                  const __nv_bfloat16* __restrict__ inL,
                  const __nv_bfloat16* __restrict__ w1img,
                  const __nv_bfloat16* __restrict__ w2img,
                  __nv_bfloat16* __restrict__ outH,
                  __nv_bfloat16* __restrict__ outL,
                  int M)
{
    constexpr int THREADS = 256, KT = 10, WSTR = 168;
    constexpr int S1 = 10 * KT * 512;              // 51200 B per plane
    constexpr int OFF_SB2 = 2 * S1;                // 20480 B
    constexpr int OFF_A = OFF_SB2 + 20480;         // 40960 B
    constexpr int OFF_INT = OFF_A + 40960;         // 40960 B

    extern __shared__ unsigned char smem[];
    const uint32_t sbu = smem_u32(smem);
    const int tid = threadIdx.x, wid = tid >> 5, lane = tid & 31;
    const int g = lane >> 2, tg = lane & 3;
    // G1 2-D mapping
    const int mh = wid & 1, np = wid >> 1;
    const int sl0 = np * 2, sb0 = mh * 2;
    const int ssl1 = 8 + (np & 1);
    const int shi1 = np >> 1;
    // G2 warp=slice mapping
    const int ssg = 8 + (wid >> 2), sug = wid & 3;

    const ushort* W1H = (const ushort*)w1img;
    const ushort* W1L = W1H + 160 * WSTR;
    const ushort* W2H = (const ushort*)w2img;
    const ushort* W2L = W2H + 160 * WSTR;

    {
        uint4* ch = (uint4*)(smem);
        uint4* cl = (uint4*)(smem + S1);
        for (int s = wid; s < 10; s += 8) {
            for (int k0 = 0; k0 < KT; k0++) {
                uint32_t bh[4], bl[4];
                wfrag(W1H, W1L, WSTR, k0, s, g, tg, bh, bl);
                ch[(s*KT + k0)*32 + lane] = make_uint4(bh[0], bh[1], bh[2], bh[3]);
                cl[(s*KT + k0)*32 + lane] = make_uint4(bl[0], bl[1], bl[2], bl[3]);
            }
        }
    }
    if (wid < 2) {
        uint4* sb = (uint4*)(smem + OFF_SB2);
        int slice = 8 + wid;
        for (int k0 = 0; k0 < KT; k0++) {
            uint32_t bh[4], bl[4];
            wfrag(W2H, W2L, WSTR, k0, slice, g, tg, bh, bl);
            sb[(wid*KT + k0)*32 + lane]       = make_uint4(bh[0], bh[1], bh[2], bh[3]);
            sb[640 + (wid*KT + k0)*32 + lane] = make_uint4(bl[0], bl[1], bl[2], bl[3]);
        }
    }
    uint32_t pbh[KT][4], pbl[KT][4];
#pragma unroll
    for (int k0 = 0; k0 < KT; k0++)
        wfrag(W2H, W2L, WSTR, k0, wid, g, tg, pbh[k0], pbl[k0]);
    __syncthreads();

    const uint4* c1h = (const uint4*)(smem);
    const uint4* c1l = (const uint4*)(smem + S1);
    const uint4* sb2 = (const uint4*)(smem + OFF_SB2);
    const int ntiles = (M + 63) >> 6;

    auto stage = [&](int tile) {
        const uint4* hp = (const uint4*)inH;
        const uint4* lp = (const uint4*)inL;
        for (int i = tid; i < 2560; i += THREADS) {
            int plane = i / 1280, off = i - plane * 1280;
            const uint4* s = (plane ? lp : hp) + (size_t)tile * 1280 + off;
            cpa16(sbu + OFF_A + plane * 20480 + off * 16, s);
        }
        CP_COMMIT();
    };

    int tile = blockIdx.x;
    if (tile < ntiles) stage(tile);

    for (; tile < ntiles; tile += gridDim.x) {
        CP_WAIT0();
        __syncthreads();

        // ---- G1: 2-D, k0-outer ------------------------------------------------
        {
            const uint4* ap = (const uint4*)(smem + OFF_A);
            float am[2][2][2][4] = {};   // [si][s2][nh]
            float as[2][4] = {};
#pragma unroll
            for (int k0 = 0; k0 < KT; k0++) {
                uint32_t aH[2][4], aL[2][4];
#pragma unroll
                for (int si = 0; si < 2; si++) {
                    uint4 a4 = ap[(k0*4 + sb0 + si)*32 + lane];
                    uint4 b4 = ap[1280 + (k0*4 + sb0 + si)*32 + lane];
                    aH[si][0]=a4.x; aH[si][1]=a4.y; aH[si][2]=a4.z; aH[si][3]=a4.w;
                    aL[si][0]=b4.x; aL[si][1]=b4.y; aL[si][2]=b4.z; aL[si][3]=b4.w;
                }
#pragma unroll
                for (int s2 = 0; s2 < 2; s2++) {
                    uint4 h4 = c1h[((sl0+s2)*KT + k0)*32 + lane];
                    uint4 l4 = c1l[((sl0+s2)*KT + k0)*32 + lane];
#pragma unroll
                    for (int si = 0; si < 2; si++) {
                        mma_bf16(am[si][s2][0], aH[si], h4.x, h4.y);
                        mma_bf16(am[si][s2][0], aH[si], l4.x, l4.y);
                        mma_bf16(am[si][s2][0], aL[si], h4.x, h4.y);
                        mma_bf16(am[si][s2][1], aH[si], h4.z, h4.w);
                        mma_bf16(am[si][s2][1], aH[si], l4.z, l4.w);
                        mma_bf16(am[si][s2][1], aL[si], h4.z, h4.w);
                    }
                }
                {
                    uint4 h4 = c1h[(ssl1*KT + k0)*32 + lane];
                    uint4 l4 = c1l[(ssl1*KT + k0)*32 + lane];
                    mma_bf16(as[0], aH[shi1], h4.x, h4.y);
                    mma_bf16(as[0], aH[shi1], l4.x, l4.y);
                    mma_bf16(as[0], aL[shi1], h4.x, h4.y);
                    mma_bf16(as[1], aH[shi1], h4.z, h4.w);
                    mma_bf16(as[1], aH[shi1], l4.z, l4.w);
                    mma_bf16(as[1], aL[shi1], h4.z, h4.w);
                }
            }
            uint4* ih = (uint4*)(smem + OFF_INT);
#pragma unroll
            for (int si = 0; si < 2; si++)
#pragma unroll
                for (int s2 = 0; s2 < 2; s2++) {
                    uint4 hv, lv;
                    pack_epi(am[si][s2][0], am[si][s2][1], sl0 + s2, tg, hv, lv);
                    ih[((sl0+s2)*4 + sb0 + si)*32 + lane]        = hv;
                    ih[1280 + ((sl0+s2)*4 + sb0 + si)*32 + lane] = lv;
                }
            {
                uint4 hv, lv;
                pack_epi(as[0], as[1], ssl1, tg, hv, lv);
                ih[(ssl1*4 + sb0 + shi1)*32 + lane]        = hv;
                ih[1280 + (ssl1*4 + sb0 + shi1)*32 + lane] = lv;
            }
        }
        __syncthreads();

        int nxt = tile + gridDim.x;
        if (nxt < ntiles) stage(nxt);

        // ---- G2: warp=slice, k0-outer, all 5 units fused -----------------------
        {
            const uint4* ip = (const uint4*)(smem + OFF_INT);
            float am[4][2][4] = {};
            float as[2][4] = {};
            const int scg = ssg - 8;
#pragma unroll
            for (int k0 = 0; k0 < KT; k0++) {
                uint32_t aH[4][4], aL[4][4];
#pragma unroll
                for (int sub = 0; sub < 4; sub++) {
                    uint4 a4 = ip[(k0*4 + sub)*32 + lane];
                    uint4 b4 = ip[1280 + (k0*4 + sub)*32 + lane];
                    aH[sub][0]=a4.x; aH[sub][1]=a4.y; aH[sub][2]=a4.z; aH[sub][3]=a4.w;
                    aL[sub][0]=b4.x; aL[sub][1]=b4.y; aL[sub][2]=b4.z; aL[sub][3]=b4.w;
                }
#pragma unroll
                for (int sub = 0; sub < 4; sub++) {
                    mma_bf16(am[sub][0], aH[sub], pbh[k0][0], pbh[k0][1]);
                    mma_bf16(am[sub][0], aH[sub], pbl[k0][0], pbl[k0][1]);
                    mma_bf16(am[sub][0], aL[sub], pbh[k0][0], pbh[k0][1]);
                    mma_bf16(am[sub][1], aH[sub], pbh[k0][2], pbh[k0][3]);
                    mma_bf16(am[sub][1], aH[sub], pbl[k0][2], pbl[k0][3]);
                    mma_bf16(am[sub][1], aL[sub], pbh[k0][2], pbh[k0][3]);
                }
                {
                    uint4 h4 = sb2[(scg*KT + k0)*32 + lane];
                    uint4 l4 = sb2[640 + (scg*KT + k0)*32 + lane];
                    mma_bf16(as[0], aH[sug], h4.x, h4.y);
                    mma_bf16(as[0], aH[sug], l4.x, l4.y);
                    mma_bf16(as[0], aL[sug], h4.x, h4.y);
                    mma_bf16(as[1], aH[sug], h4.z, h4.w);
                    mma_bf16(as[1], aH[sug], l4.z, l4.w);
                    mma_bf16(as[1], aL[sug], h4.z, h4.w);
                }
            }
            uint4* oh = (uint4*)outH;
            uint4* ol = (uint4*)outL;
#pragma unroll
            for (int sub = 0; sub < 4; sub++) {
                uint4 hv, lv;
                pack_epi(am[sub][0], am[sub][1], wid, tg, hv, lv);
                size_t base = ((size_t)tile * 40 + wid * 4 + sub) * 32 + lane;
                oh[base] = hv;
                ol[base] = lv;
            }
            {
                uint4 hv, lv;
                pack_epi(as[0], as[1], ssg, tg, hv, lv);
                size_t base = ((size_t)tile * 40 + ssg * 4 + sug) * 32 + lane;
                oh[base] = hv;
                ol[base] = lv;
            }
        }
        __syncthreads();
    }
}

// ===================== final layer + fused segment-sum (16 warps) ============
__global__ __launch_bounds__(512, 1)
void layer_atomic(const __nv_bfloat16* __restrict__ inH,
                  const __nv_bfloat16* __restrict__ inL,
                  const __nv_bfloat16* __restrict__ wimg,   // [160][72] hi,lo
                  const int* __restrict__ tgt,
                  float* __restrict__ ep,
                  int M)
{
    constexpr int THREADS = 512, KT = 10, WSTR = 72;
    constexpr int SLOT = 40960;

    extern __shared__ unsigned char smem[];
    const uint32_t sbu = smem_u32(smem);
    const int tid = threadIdx.x, wid = tid >> 5, lane = tid & 31;
    const int g = lane >> 2, tg = lane & 3;
    const int warp_n = wid & 3, sub = wid >> 2;

    uint32_t pbh[KT][4], pbl[KT][4];
    {
        const ushort* WH = (const ushort*)wimg;
        const ushort* WL = WH + 160 * WSTR;
#pragma unroll
        for (int k0 = 0; k0 < KT; k0++)
            wfrag(WH, WL, WSTR, k0, warp_n, g, tg, pbh[k0], pbl[k0]);
    }

    const int ntiles = (M + 63) >> 6;
    const uint4* hp = (const uint4*)inH;
    const uint4* lp = (const uint4*)inL;

    auto stage = [&](int slot, int tile) {
        if (tile < ntiles) {
            for (int i = tid; i < 2560; i += THREADS) {
                int plane = i / 1280, off = i - plane * 1280;
                const uint4* s = (plane ? lp : hp) + (size_t)tile * 1280 + off;
                cpa16(sbu + slot * SLOT + plane * 20480 + off * 16, s);
            }
        }
        CP_COMMIT();
    };

    int t0 = blockIdx.x;
    stage(0, t0);
    stage(1, t0 + gridDim.x);

    int i = 0;
    for (int t = t0; t < ntiles; t += gridDim.x, i++) {
        CP_WAIT1();
        __syncthreads();
        stage((i + 2) % 3, t + 2 * gridDim.x);

        const uint4* ap = (const uint4*)(smem + (i % 3) * SLOT);
        const size_t row0 = (size_t)t << 6;

        float acc[2][4] = {};
#pragma unroll
        for (int k0 = 0; k0 < KT; k0++) {
            uint4 a4 = ap[(k0*4 + sub)*32 + lane];
            uint4 b4 = ap[1280 + (k0*4 + sub)*32 + lane];
            uint32_t aH[4] = {a4.x, a4.y, a4.z, a4.w};
            uint32_t aL[4] = {b4.x, b4.y, b4.z, b4.w};
            mma_bf16(acc[0], aH, pbh[k0][0], pbh[k0][1]);
            mma_bf16(acc[0], aH, pbl[k0][0], pbl[k0][1]);
            mma_bf16(acc[0], aL, pbh[k0][0], pbh[k0][1]);
            mma_bf16(acc[1], aH, pbh[k0][2], pbh[k0][3]);
            mma_bf16(acc[1], aH, pbl[k0][2], pbl[k0][3]);
            mma_bf16(acc[1], aL, pbh[k0][2], pbh[k0][3]);
        }
        size_t gr0 = row0 + sub * 16 + g;
        size_t gr1 = gr0 + 8;
        int t0i = (gr0 < (size_t)M) ? __ldg(tgt + gr0) : -1;
        int t1i = (gr1 < (size_t)M) ? __ldg(tgt + gr1) : -1;
#pragma unroll
        for (int nh = 0; nh < 2; nh++) {
            int gc = warp_n * 16 + nh * 8 + tg * 2;
            if (gc < 50) {
                if (t0i >= 0) red2(ep + (size_t)t0i * 64 + gc, acc[nh][0], acc[nh][1]);
                if (t1i >= 0) red2(ep + (size_t)t1i * 64 + gc, acc[nh][2], acc[nh][3]);
            }
        }
    }
}

// ===================== SIMT GEMM (node MLP) =================================
template <int NS>
__global__ __launch_bounds__(256, 2)
void gemm_kernel(const float* __restrict__ A, int lda,
                 const float* __restrict__ W, const float* __restrict__ B,
                 float* __restrict__ C, int ldc,
                 int M, int din, int dout, int relu, int padstore)
{
    constexpr int PN = NS * 32;
    extern __shared__ float sm[];
    float* Ws = sm;
    float* Bs = Ws + ((din + 3) & ~3) * PN;
    const int tid = threadIdx.x;
    const int din4 = (din + 3) & ~3;
    for (int idx = tid; idx < din4 * PN; idx += 256) {
        int k = idx / PN, j = idx - k * PN;
        Ws[idx] = (k < din && j < dout) ? W[(size_t)k * dout + j] : 0.f;
    }
    for (int j = tid; j < PN; j += 256) Bs[j] = (j < dout) ? B[j] : 0.f;
    __syncthreads();
    const int lane = tid & 31;
    const int gwarp = blockIdx.x * 8 + (tid >> 5);
    const int nwarp = gridDim.x * 8;
    for (int sidx = gwarp; sidx < (M + 7) >> 3; sidx += nwarp) {
        const int row0 = sidx << 3;
        const float* ap[8];
#pragma unroll
        for (int r = 0; r < 8; r++) {
            int rr = row0 + r; if (rr > M - 1) rr = M - 1;
            ap[r] = A + (size_t)rr * lda;
        }
        float acc[8][NS];
#pragma unroll
        for (int r = 0; r < 8; r++)
#pragma unroll
            for (int s = 0; s < NS; s++) acc[r][s] = 0.f;
#pragma unroll 2
        for (int k = 0; k < din4; k += 4) {
            float4 a[8];
#pragma unroll
            for (int r = 0; r < 8; r++) a[r] = *(const float4*)(ap[r] + k);
#pragma unroll
            for (int kk = 0; kk < 4; kk++) {
                float wv[NS];
#pragma unroll
                for (int s = 0; s < NS; s++) wv[s] = Ws[(k + kk) * PN + lane + (s << 5)];
#pragma unroll
                for (int r = 0; r < 8; r++) {
                    float av = (kk == 0) ? a[r].x : (kk == 1) ? a[r].y : (kk == 2) ? a[r].z : a[r].w;
#pragma unroll
                    for (int s = 0; s < NS; s++) acc[r][s] = fmaf(av, wv[s], acc[r][s]);
                }
            }
        }
#pragma unroll
        for (int r = 0; r < 8; r++) {
            int row = row0 + r;
            if (row < M) {
#pragma unroll
                for (int s = 0; s < NS; s++) {
                    int j = lane + (s << 5);
                    float v = acc[r][s] + Bs[j];
                    if (relu) v = fmaxf(v, 0.f);
                    if (padstore || j < dout) C[(size_t)row * ldc + j] = v;
                }
            }
        }
    }
}

// ===================== host ==================================================
static inline size_t smbytes(int din, int PN)
{
    int din4 = (din + 3) & ~3;
    return (size_t)(din4 * PN + PN) * sizeof(float);
}

extern "C" void kernel_launch(void* const* d_in, const int* in_sizes, int n_in,
                              void* d_out, int out_size)
{
    const float* t   = (const float*)d_in[0];
    const float* x   = (const float*)d_in[1];
    const float* ofx = (const float*)d_in[2];
    const int* src   = (const int*)d_in[3];
    const int* tgt   = (const int*)d_in[4];
    const float* RW[5] = {(const float*)d_in[5], (const float*)d_in[7], (const float*)d_in[9],
                          (const float*)d_in[11], (const float*)d_in[13]};
    const float* Rb[5] = {(const float*)d_in[6], (const float*)d_in[8], (const float*)d_in[10],
                          (const float*)d_in[12], (const float*)d_in[14]};
    const float* OW0 = (const float*)d_in[15];
    const float* Ob0 = (const float*)d_in[16];
    const float* OW1 = (const float*)d_in[17];
    const float* Ob1 = (const float*)d_in[18];
    float* out = (float*)d_out;

    const int M = in_sizes[3];
    const int N = in_sizes[1] / 4;

    __nv_bfloat16 *rpH, *rpL, *Xh, *Xl, *Yh, *Yl, *wst;
    float* ep;
    cudaGetSymbolAddress((void**)&rpH, g_rpH);
    cudaGetSymbolAddress((void**)&rpL, g_rpL);
    cudaGetSymbolAddress((void**)&Xh,  g_Xh);
    cudaGetSymbolAddress((void**)&Xl,  g_Xl);
    cudaGetSymbolAddress((void**)&Yh,  g_Yh);
    cudaGetSymbolAddress((void**)&Yl,  g_Yl);
    cudaGetSymbolAddress((void**)&ep,  g_eprime);
    cudaGetSymbolAddress((void**)&wst, g_wstage);

    int nsm = 148;
    cudaDeviceGetAttribute(&nsm, cudaDevAttrMultiProcessorCount, 0);

    const int woff[5] = {0, 5376, 59136, 112896, 166656};
    const int wdin[5]  = {13, 150, 150, 150, 150};
    const int wdout[5] = {150, 150, 150, 150, 50};
    const int wKD[5]   = {16, 160, 160, 160, 160};
    const int wWSTR[5] = {168, 168, 168, 168, 72};
    const int wbrow[5] = {13, 150, 150, 150, 150};
    PrepPack pk;
    int ptotal = 0;
    for (int i = 0; i < 5; i++) {
        pk.c[i] = PrepCfg{RW[i], Rb[i], wdin[i], wdout[i], wKD[i], wWSTR[i], wbrow[i], woff[i]};
        ptotal += wKD[i] * wWSTR[i];
    }
    prep_all<<<(ptotal + 255) / 256, 256>>>(pk, wst, ptotal);

    zero_kernel<<<(N * 64 + 255) / 256, 256>>>(ep, N * 64);
    gather_kernel<<<(M + 255) / 256, 256>>>(x, ofx, src, tgt, t, rpH, rpL, M);

    const int sm01 = 81920 + 51200 + 10240;                 // 143360
    const int sm23 = 2*51200 + 20480 + 40960 + 40960;       // 204800
    const int sm4  = 3 * 40960;                             // 122880
    cudaFuncSetAttribute(pair1_kernel, cudaFuncAttributeMaxDynamicSharedMemorySize, sm01);
    cudaFuncSetAttribute(pair2_kernel, cudaFuncAttributeMaxDynamicSharedMemorySize, sm23);
    cudaFuncSetAttribute(layer_atomic, cudaFuncAttributeMaxDynamicSharedMemorySize, sm4);

    pair1_kernel<<<nsm, 256, sm01>>>(rpH, rpL, wst + woff[0], wst + woff[1], Xh, Xl, M);
    pair2_kernel<<<nsm, 256, sm23>>>(Xh, Xl, wst + woff[2], wst + woff[3], Yh, Yl, M);
    layer_atomic<<<nsm, 512, sm4>>>(Yh, Yl, wst + woff[4], tgt, ep, M);

    cudaFuncSetAttribute(gemm_kernel<4>, cudaFuncAttributeMaxDynamicSharedMemorySize, 112 * 1024);
    cudaFuncSetAttribute(gemm_kernel<1>, cudaFuncAttributeMaxDynamicSharedMemorySize, 112 * 1024);
    float* nb = (float*)rpH;
    gemm_kernel<4><<<2 * nsm, 256, smbytes(50, 128)>>>(ep, 64, OW0, Ob0, nb, 128, N, 50, 100, 1, 1);
    gemm_kernel<1><<<2 * nsm, 256, smbytes(100, 32)>>>(nb, 128, OW1, Ob1, out, 4, N, 100, 4, 0, 0);
}

// round 16
// speedup vs baseline: 1.5027x; 1.5027x over previous
#include <cuda_runtime.h>
#include <cuda_bf16.h>
#include <cstdint>
#include <cstddef>

// ===================== scratch (no allocations allowed) =====================
#define MAX_EDGES 2000000
#define MAX_NODES 100000
#define SLACK 128

__device__ __align__(128) __nv_bfloat16 g_rpH[(size_t)(MAX_EDGES + SLACK) * 16];
__device__ __align__(128) __nv_bfloat16 g_rpL[(size_t)(MAX_EDGES + SLACK) * 16];
__device__ __align__(128) __nv_bfloat16 g_Xh[(size_t)(MAX_EDGES + SLACK) * 160];
__device__ __align__(128) __nv_bfloat16 g_Xl[(size_t)(MAX_EDGES + SLACK) * 160];
__device__ __align__(128) __nv_bfloat16 g_Yh[(size_t)(MAX_EDGES + SLACK) * 160];
__device__ __align__(128) __nv_bfloat16 g_Yl[(size_t)(MAX_EDGES + SLACK) * 160];
__device__ float g_eprime[(size_t)MAX_NODES * 64];
__device__ __align__(128) __nv_bfloat16 g_wstage[262144];

// ===================== low-level helpers =====================================
__device__ __forceinline__ uint32_t smem_u32(const void* p) {
    uint32_t a;
    asm("{ .reg .u64 t; cvta.to.shared.u64 t, %1; cvt.u32.u64 %0, t; }" : "=r"(a) : "l"(p));
    return a;
}
__device__ __forceinline__ void cpa16(uint32_t dst, const void* src) {
    asm volatile("cp.async.cg.shared.global [%0], [%1], 16;" :: "r"(dst), "l"(src));
}
#define CP_COMMIT() asm volatile("cp.async.commit_group;" ::: "memory")
#define CP_WAIT0()  asm volatile("cp.async.wait_group 0;" ::: "memory")
#define CP_WAIT1()  asm volatile("cp.async.wait_group 1;" ::: "memory")

__device__ __forceinline__ void mma_bf16(float* c, const uint32_t* a, uint32_t b0, uint32_t b1) {
    asm volatile(
        "mma.sync.aligned.m16n8k16.row.col.f32.bf16.bf16.f32 "
        "{%0,%1,%2,%3}, {%4,%5,%6,%7}, {%8,%9}, {%0,%1,%2,%3};"
        : "+f"(c[0]), "+f"(c[1]), "+f"(c[2]), "+f"(c[3])
        : "r"(a[0]), "r"(a[1]), "r"(a[2]), "r"(a[3]), "r"(b0), "r"(b1));
}
__device__ __forceinline__ void red2(float* gp, float v0, float v1) {
    asm volatile("red.global.add.v2.f32 [%0], {%1, %2};" :: "l"(gp), "f"(v0), "f"(v1) : "memory");
}
__device__ __forceinline__ void split2(float v0, float v1, uint32_t& hi, uint32_t& lo) {
    __nv_bfloat16 h0 = __float2bfloat16(v0), h1 = __float2bfloat16(v1);
    __nv_bfloat16 l0 = __float2bfloat16(v0 - __bfloat162float(h0));
    __nv_bfloat16 l1 = __float2bfloat16(v1 - __bfloat162float(h1));
    hi = (uint32_t)__bfloat16_as_ushort(h0) | ((uint32_t)__bfloat16_as_ushort(h1) << 16);
    lo = (uint32_t)__bfloat16_as_ushort(l0) | ((uint32_t)__bfloat16_as_ushort(l1) << 16);
}

// pack acc -> hi/lo uint4 with relu + col150=1
__device__ __forceinline__ void pack_epi(const float* a0, const float* a1, int slice, int tg,
                                         uint4& hv, uint4& lv) {
    uint32_t ph[4], pl[4];
#pragma unroll
    for (int nh = 0; nh < 2; nh++) {
        const float* a = nh ? a1 : a0;
        float v0 = fmaxf(a[0], 0.f);
        float v1 = fmaxf(a[1], 0.f);
        float v2 = fmaxf(a[2], 0.f);
        float v3 = fmaxf(a[3], 0.f);
        int gc = slice * 16 + nh * 8 + tg * 2;
        if (gc == 150)     { v0 = 1.f; v2 = 1.f; }
        if (gc + 1 == 150) { v1 = 1.f; v3 = 1.f; }
        split2(v0, v1, ph[nh*2],   pl[nh*2]);
        split2(v2, v3, ph[nh*2+1], pl[nh*2+1]);
    }
    hv = make_uint4(ph[0], ph[1], ph[2], ph[3]);
    lv = make_uint4(pl[0], pl[1], pl[2], pl[3]);
}

// ===================== merged weight prep ====================================
struct PrepCfg {
    const float* W; const float* b;
    int din, dout, KD, WSTR, brow, off;
};
struct PrepPack { PrepCfg c[5]; };

__global__ void prep_all(PrepPack p, __nv_bfloat16* __restrict__ wst, int total)
{
    int idx = blockIdx.x * blockDim.x + threadIdx.x;
    if (idx >= total) return;
#pragma unroll
    for (int L = 0; L < 5; L++) {
        int tot = p.c[L].KD * p.c[L].WSTR;
        if (idx < tot) {
            int k = idx / p.c[L].WSTR, n = idx - k * p.c[L].WSTR;
            float v = 0.f;
            if (n < p.c[L].dout) {
                if (k < p.c[L].din) v = p.c[L].W[(size_t)k * p.c[L].dout + n];
                else if (k == p.c[L].brow) v = p.c[L].b[n];
            }
            __nv_bfloat16 h = __float2bfloat16(v);
            __nv_bfloat16 l = __float2bfloat16(v - __bfloat162float(h));
            wst[p.c[L].off + idx] = h;
            wst[p.c[L].off + tot + idx] = l;
            return;
        }
        idx -= tot;
    }
}

// B fragment gather from weight image (ushort layout [KD][WSTR], hi then lo)
__device__ __forceinline__ void wfrag(const ushort* WH, const ushort* WL, int WSTR,
                                      int k0, int slice, int g, int tg,
                                      uint32_t* bh, uint32_t* bl) {
#pragma unroll
    for (int nh = 0; nh < 2; nh++)
#pragma unroll
        for (int r = 0; r < 2; r++) {
            int k = k0 * 16 + tg * 2 + r * 8;
            int n = slice * 16 + nh * 8 + g;
            bh[nh*2+r] = (uint32_t)WH[k*WSTR+n] | ((uint32_t)WH[(k+1)*WSTR+n] << 16);
            bl[nh*2+r] = (uint32_t)WL[k*WSTR+n] | ((uint32_t)WL[(k+1)*WSTR+n] << 16);
        }
}

// ===================== gather ================================================
__global__ void gather_kernel(const float* __restrict__ x,
                              const float* __restrict__ ofx,
                              const int* __restrict__ src,
                              const int* __restrict__ tgt,
                              const float* __restrict__ t,
                              __nv_bfloat16* __restrict__ oh,
                              __nv_bfloat16* __restrict__ ol, int M)
{
    int e = blockIdx.x * blockDim.x + threadIdx.x;
    if (e >= M) return;
    int s = src[e], g = tgt[e];
    float v[16];
    float4 xs = *(const float4*)(x + (size_t)4 * s);
    float2 os = *(const float2*)(ofx + (size_t)2 * s);
    float4 xt = *(const float4*)(x + (size_t)4 * g);
    float2 ot = *(const float2*)(ofx + (size_t)2 * g);
    v[0]=xs.x; v[1]=xs.y; v[2]=xs.z; v[3]=xs.w; v[4]=os.x; v[5]=os.y;
    v[6]=xt.x; v[7]=xt.y; v[8]=xt.z; v[9]=xt.w; v[10]=ot.x; v[11]=ot.y;
    v[12]=t[0]; v[13]=1.0f; v[14]=0.f; v[15]=0.f;
    uint32_t wh[8], wl[8];
#pragma unroll
    for (int i = 0; i < 8; i++) split2(v[2*i], v[2*i+1], wh[i], wl[i]);
    uint4* ph = (uint4*)(oh + (size_t)e * 16);
    uint4* pl = (uint4*)(ol + (size_t)e * 16);
    ph[0] = make_uint4(wh[0], wh[1], wh[2], wh[3]);
    ph[1] = make_uint4(wh[4], wh[5], wh[6], wh[7]);
    pl[0] = make_uint4(wl[0], wl[1], wl[2], wl[3]);
    pl[1] = make_uint4(wl[4], wl[5], wl[6], wl[7]);
}

__global__ void zero_kernel(float* __restrict__ p, int n)
{
    int i = blockIdx.x * blockDim.x + threadIdx.x;
    if (i < n) p[i] = 0.f;
}

// ===================== pair1: L0+L1 fused, 8 warps, reduced regs =============
// B2 split: k0 0..4 in regs (40), k0 5..9 in smem cache RB2 (all 10 slices).
__global__ __launch_bounds__(256, 1)
void pair1_kernel(const __nv_bfloat16* __restrict__ rpH,
                  const __nv_bfloat16* __restrict__ rpL,
                  const __nv_bfloat16* __restrict__ w1img,   // [16][168] hi,lo
                  const __nv_bfloat16* __restrict__ w2img,   // [160][168] hi,lo
                  __nv_bfloat16* __restrict__ outH,
                  __nv_bfloat16* __restrict__ outL,
                  int M)
{
    constexpr int WSTR = 168;
    extern __shared__ unsigned char smem[];
    uint4* INT = (uint4*)smem;                       // 2 bufs x 2560 uint4
    uint4* RB2 = (uint4*)(smem + 81920);             // [10][5][32] hi(1600), lo(+1600)
    uint4* SB2 = (uint4*)(smem + 133120);            // [2][5][32] hi(320), lo(+320)

    const int tid = threadIdx.x, wid = tid >> 5, lane = tid & 31;
    const int g = lane >> 2, tg = lane & 3;
    const int ss = 8 + (wid >> 2);                   // shared slice (8 or 9)
    const int su = wid & 3;                          // shared sub
    const int sc = ss - 8;

    const ushort* W1H = (const ushort*)w1img;
    const ushort* W1L = W1H + 16 * WSTR;
    const ushort* W2H = (const ushort*)w2img;
    const ushort* W2L = W2H + 160 * WSTR;

    // B1 regs: main slice (wid) + shared slice (ss)
    uint32_t b1hm[4], b1lm[4], b1hs[4], b1ls[4];
    wfrag(W1H, W1L, WSTR, 0, wid, g, tg, b1hm, b1lm);
    wfrag(W1H, W1L, WSTR, 0, ss,  g, tg, b1hs, b1ls);

    // B2 regs: main slice, k0 0..4 only
    uint32_t pbh[5][4], pbl[5][4];
#pragma unroll
    for (int k0 = 0; k0 < 5; k0++)
        wfrag(W2H, W2L, WSTR, k0, wid, g, tg, pbh[k0], pbl[k0]);

    // RB2 cache: all 10 slices, k0 5..9 (warp w builds slices w, w+8)
    for (int s = wid; s < 10; s += 8) {
        for (int k0 = 5; k0 < 10; k0++) {
            uint32_t bh[4], bl[4];
            wfrag(W2H, W2L, WSTR, k0, s, g, tg, bh, bl);
            RB2[(s*5 + k0 - 5)*32 + lane]        = make_uint4(bh[0], bh[1], bh[2], bh[3]);
            RB2[1600 + (s*5 + k0 - 5)*32 + lane] = make_uint4(bl[0], bl[1], bl[2], bl[3]);
        }
    }
    // SB2 cache: slices 8,9 k0 0..4 (warps 0,1)
    if (wid < 2) {
        int slice = 8 + wid;
        for (int k0 = 0; k0 < 5; k0++) {
            uint32_t bh[4], bl[4];
            wfrag(W2H, W2L, WSTR, k0, slice, g, tg, bh, bl);
            SB2[(wid*5 + k0)*32 + lane]       = make_uint4(bh[0], bh[1], bh[2], bh[3]);
            SB2[320 + (wid*5 + k0)*32 + lane] = make_uint4(bl[0], bl[1], bl[2], bl[3]);
        }
    }
    __syncthreads();

    const int ntiles = (M + 63) >> 6;

    uint32_t pAH[4][4], pAL[4][4];   // A frags for all 4 subs
    auto loadA = [&](int tile) {
        const int row0 = tile << 6;
#pragma unroll
        for (int sub = 0; sub < 4; sub++) {
            int r0 = row0 + sub * 16 + g;
            int r1 = r0 + 8;
            if (r0 > M - 1) r0 = M - 1;
            if (r1 > M - 1) r1 = M - 1;
            const __nv_bfloat16* h0p = rpH + (size_t)r0 * 16 + tg * 2;
            const __nv_bfloat16* h1p = rpH + (size_t)r1 * 16 + tg * 2;
            const __nv_bfloat16* l0p = rpL + (size_t)r0 * 16 + tg * 2;
            const __nv_bfloat16* l1p = rpL + (size_t)r1 * 16 + tg * 2;
            pAH[sub][0] = *(const uint32_t*)h0p;
            pAH[sub][1] = *(const uint32_t*)h1p;
            pAH[sub][2] = *(const uint32_t*)(h0p + 8);
            pAH[sub][3] = *(const uint32_t*)(h1p + 8);
            pAL[sub][0] = *(const uint32_t*)l0p;
            pAL[sub][1] = *(const uint32_t*)l1p;
            pAL[sub][2] = *(const uint32_t*)(l0p + 8);
            pAL[sub][3] = *(const uint32_t*)(l1p + 8);
        }
    };

    auto g1 = [&](int buf) {
        uint4* ih = INT + buf * 2560;
#pragma unroll
        for (int sub = 0; sub < 4; sub++) {
            float acc[2][4] = {};
            mma_bf16(acc[0], pAH[sub], b1hm[0], b1hm[1]);
            mma_bf16(acc[0], pAH[sub], b1lm[0], b1lm[1]);
            mma_bf16(acc[0], pAL[sub], b1hm[0], b1hm[1]);
            mma_bf16(acc[1], pAH[sub], b1hm[2], b1hm[3]);
            mma_bf16(acc[1], pAH[sub], b1lm[2], b1lm[3]);
            mma_bf16(acc[1], pAL[sub], b1hm[2], b1hm[3]);
            uint4 hv, lv;
            pack_epi(acc[0], acc[1], wid, tg, hv, lv);
            ih[(wid*4 + sub)*32 + lane]        = hv;
            ih[1280 + (wid*4 + sub)*32 + lane] = lv;
        }
        {   // shared unit (slice ss, sub su)
            float acc[2][4] = {};
            mma_bf16(acc[0], pAH[su], b1hs[0], b1hs[1]);
            mma_bf16(acc[0], pAH[su], b1ls[0], b1ls[1]);
            mma_bf16(acc[0], pAL[su], b1hs[0], b1hs[1]);
            mma_bf16(acc[1], pAH[su], b1hs[2], b1hs[3]);
            mma_bf16(acc[1], pAH[su], b1ls[2], b1ls[3]);
            mma_bf16(acc[1], pAL[su], b1hs[2], b1hs[3]);
            uint4 hv, lv;
            pack_epi(acc[0], acc[1], ss, tg, hv, lv);
            ih[(ss*4 + su)*32 + lane]        = hv;
            ih[1280 + (ss*4 + su)*32 + lane] = lv;
        }
    };

    auto g2 = [&](int tile, int buf) {
        const uint4* ip = INT + buf * 2560;
        uint4* oh = (uint4*)outH;
        uint4* ol = (uint4*)outL;
#pragma unroll
        for (int sub = 0; sub < 4; sub++) {
            float acc[2][4] = {};
#pragma unroll
            for (int k0 = 0; k0 < 5; k0++) {
                uint4 a4 = ip[(k0*4 + sub)*32 + lane];
                uint4 b4 = ip[1280 + (k0*4 + sub)*32 + lane];
                uint32_t aH[4] = {a4.x, a4.y, a4.z, a4.w};
                uint32_t aL[4] = {b4.x, b4.y, b4.z, b4.w};
                mma_bf16(acc[0], aH, pbh[k0][0], pbh[k0][1]);
                mma_bf16(acc[0], aH, pbl[k0][0], pbl[k0][1]);
                mma_bf16(acc[0], aL, pbh[k0][0], pbh[k0][1]);
                mma_bf16(acc[1], aH, pbh[k0][2], pbh[k0][3]);
                mma_bf16(acc[1], aH, pbl[k0][2], pbl[k0][3]);
                mma_bf16(acc[1], aL, pbh[k0][2], pbh[k0][3]);
            }
#pragma unroll
            for (int k0 = 5; k0 < 10; k0++) {
                uint4 a4 = ip[(k0*4 + sub)*32 + lane];
                uint4 b4 = ip[1280 + (k0*4 + sub)*32 + lane];
                uint32_t aH[4] = {a4.x, a4.y, a4.z, a4.w};
                uint32_t aL[4] = {b4.x, b4.y, b4.z, b4.w};
                uint4 h4 = RB2[(wid*5 + k0 - 5)*32 + lane];
                uint4 l4 = RB2[1600 + (wid*5 + k0 - 5)*32 + lane];
                mma_bf16(acc[0], aH, h4.x, h4.y);
                mma_bf16(acc[0], aH, l4.x, l4.y);
                mma_bf16(acc[0], aL, h4.x, h4.y);
                mma_bf16(acc[1], aH, h4.z, h4.w);
                mma_bf16(acc[1], aH, l4.z, l4.w);
                mma_bf16(acc[1], aL, h4.z, h4.w);
            }
            uint4 hv, lv;
            pack_epi(acc[0], acc[1], wid, tg, hv, lv);
            size_t base = ((size_t)tile * 40 + wid * 4 + sub) * 32 + lane;
            oh[base] = hv;
            ol[base] = lv;
        }
        {   // shared unit
            float acc[2][4] = {};
#pragma unroll
            for (int k0 = 0; k0 < 5; k0++) {
                uint4 a4 = ip[(k0*4 + su)*32 + lane];
                uint4 b4 = ip[1280 + (k0*4 + su)*32 + lane];
                uint32_t aH[4] = {a4.x, a4.y, a4.z, a4.w};
                uint32_t aL[4] = {b4.x, b4.y, b4.z, b4.w};
                uint4 h4 = SB2[(sc*5 + k0)*32 + lane];
                uint4 l4 = SB2[320 + (sc*5 + k0)*32 + lane];
                mma_bf16(acc[0], aH, h4.x, h4.y);
                mma_bf16(acc[0], aH, l4.x, l4.y);
                mma_bf16(acc[0], aL, h4.x, h4.y);
                mma_bf16(acc[1], aH, h4.z, h4.w);
                mma_bf16(acc[1], aH, l4.z, l4.w);
                mma_bf16(acc[1], aL, h4.z, h4.w);
            }
#pragma unroll
            for (int k0 = 5; k0 < 10; k0++) {
                uint4 a4 = ip[(k0*4 + su)*32 + lane];
                uint4 b4 = ip[1280 + (k0*4 + su)*32 + lane];
                uint32_t aH[4] = {a4.x, a4.y, a4.z, a4.w};
                uint32_t aL[4] = {b4.x, b4.y, b4.z, b4.w};
                uint4 h4 = RB2[(ss*5 + k0 - 5)*32 + lane];
                uint4 l4 = RB2[1600 + (ss*5 + k0 - 5)*32 + lane];
                mma_bf16(acc[0], aH, h4.x, h4.y);
                mma_bf16(acc[0], aH, l4.x, l4.y);
                mma_bf16(acc[0], aL, h4.x, h4.y);
                mma_bf16(acc[1], aH, h4.z, h4.w);
                mma_bf16(acc[1], aH, l4.z, l4.w);
                mma_bf16(acc[1], aL, h4.z, h4.w);
            }
            uint4 hv, lv;
            pack_epi(acc[0], acc[1], ss, tg, hv, lv);
            size_t base = ((size_t)tile * 40 + ss * 4 + su) * 32 + lane;
            oh[base] = hv;
            ol[base] = lv;
        }
    };

    int t = blockIdx.x;
    if (t < ntiles) { loadA(t); g1(0); }
    int i = 0;
    for (; t < ntiles; t += gridDim.x, i++) {
        int nxt = t + gridDim.x;
        if (nxt < ntiles) loadA(nxt);
        __syncthreads();
        g2(t, i & 1);
        if (nxt < ntiles) g1((i + 1) & 1);
    }
}

// ===================== pair2: L2+L3, 8 warps balanced ========================
__global__ __launch_bounds__(256, 1)
void pair2_kernel(const __nv_bfloat16* __restrict__ inH,
                  const __nv_bfloat16* __restrict__ inL,
                  const __nv_bfloat16* __restrict__ w1img,
                  const __nv_bfloat16* __restrict__ w2img,
                  __nv_bfloat16* __restrict__ outH,
                  __nv_bfloat16* __restrict__ outL,
                  int M)
{
    constexpr int THREADS = 256, KT = 10, WSTR = 168;
    constexpr int S1 = 10 * KT * 512;              // 51200 B per plane
    constexpr int OFF_SB2 = 2 * S1;                // 20480 B
    constexpr int OFF_A = OFF_SB2 + 20480;         // 40960 B
    constexpr int OFF_INT = OFF_A + 40960;         // 40960 B

    extern __shared__ unsigned char smem[];
    const uint32_t sbu = smem_u32(smem);
    const int tid = threadIdx.x, wid = tid >> 5, lane = tid & 31;
    const int g = lane >> 2, tg = lane & 3;
    const int ss = 8 + (wid >> 2), su = wid & 3;

    const ushort* W1H = (const ushort*)w1img;
    const ushort* W1L = W1H + 160 * WSTR;
    const ushort* W2H = (const ushort*)w2img;
    const ushort* W2L = W2H + 160 * WSTR;

    {
        uint4* ch = (uint4*)(smem);
        uint4* cl = (uint4*)(smem + S1);
        for (int s = wid; s < 10; s += 8) {
            for (int k0 = 0; k0 < KT; k0++) {
                uint32_t bh[4], bl[4];
                wfrag(W1H, W1L, WSTR, k0, s, g, tg, bh, bl);
                ch[(s*KT + k0)*32 + lane] = make_uint4(bh[0], bh[1], bh[2], bh[3]);
                cl[(s*KT + k0)*32 + lane] = make_uint4(bl[0], bl[1], bl[2], bl[3]);
            }
        }
    }
    if (wid < 2) {
        uint4* sb = (uint4*)(smem + OFF_SB2);
        int slice = 8 + wid;
        for (int k0 = 0; k0 < KT; k0++) {
            uint32_t bh[4], bl[4];
            wfrag(W2H, W2L, WSTR, k0, slice, g, tg, bh, bl);
            sb[(wid*KT + k0)*32 + lane]       = make_uint4(bh[0], bh[1], bh[2], bh[3]);
            sb[640 + (wid*KT + k0)*32 + lane] = make_uint4(bl[0], bl[1], bl[2], bl[3]);
        }
    }
    uint32_t pbh[KT][4], pbl[KT][4];
#pragma unroll
    for (int k0 = 0; k0 < KT; k0++)
        wfrag(W2H, W2L, WSTR, k0, wid, g, tg, pbh[k0], pbl[k0]);
    __syncthreads();

    const uint4* c1h = (const uint4*)(smem);
    const uint4* c1l = (const uint4*)(smem + S1);
    const uint4* sb2 = (const uint4*)(smem + OFF_SB2);
    const int ntiles = (M + 63) >> 6;

    auto stage = [&](int tile) {
        const uint4* hp = (const uint4*)inH;
        const uint4* lp = (const uint4*)inL;
        for (int i = tid; i < 2560; i += THREADS) {
            int plane = i / 1280, off = i - plane * 1280;
            const uint4* s = (plane ? lp : hp) + (size_t)tile * 1280 + off;
            cpa16(sbu + OFF_A + plane * 20480 + off * 16, s);
        }
        CP_COMMIT();
    };

    int tile = blockIdx.x;
    if (tile < ntiles) stage(tile);

    for (; tile < ntiles; tile += gridDim.x) {
        CP_WAIT0();
        __syncthreads();

        {
            const uint4* ap = (const uint4*)(smem + OFF_A);
            float acc[4][2][4] = {};
#pragma unroll
            for (int k0 = 0; k0 < KT; k0++) {
                uint4 h4 = c1h[(wid*KT + k0)*32 + lane];
                uint4 l4 = c1l[(wid*KT + k0)*32 + lane];
#pragma unroll
                for (int sub = 0; sub < 4; sub++) {
                    uint4 a4 = ap[(k0*4 + sub)*32 + lane];
                    uint4 b4 = ap[1280 + (k0*4 + sub)*32 + lane];
                    uint32_t aH[4] = {a4.x, a4.y, a4.z, a4.w};
                    uint32_t aL[4] = {b4.x, b4.y, b4.z, b4.w};
                    mma_bf16(acc[sub][0], aH, h4.x, h4.y);
                    mma_bf16(acc[sub][0], aH, l4.x, l4.y);
                    mma_bf16(acc[sub][0], aL, h4.x, h4.y);
                    mma_bf16(acc[sub][1], aH, h4.z, h4.w);
                    mma_bf16(acc[sub][1], aH, l4.z, l4.w);
                    mma_bf16(acc[sub][1], aL, h4.z, h4.w);
                }
            }
            uint4* ih = (uint4*)(smem + OFF_INT);
#pragma unroll
            for (int sub = 0; sub < 4; sub++) {
                uint4 hv, lv;
                pack_epi(acc[sub][0], acc[sub][1], wid, tg, hv, lv);
                ih[(wid*4 + sub)*32 + lane]        = hv;
                ih[1280 + (wid*4 + sub)*32 + lane] = lv;
            }
        }
        {
            const uint4* ap = (const uint4*)(smem + OFF_A);
            float acc[2][4] = {};
#pragma unroll
            for (int k0 = 0; k0 < KT; k0++) {
                uint4 h4 = c1h[(ss*KT + k0)*32 + lane];
                uint4 l4 = c1l[(ss*KT + k0)*32 + lane];
                uint4 a4 = ap[(k0*4 + su)*32 + lane];
                uint4 b4 = ap[1280 + (k0*4 + su)*32 + lane];
                uint32_t aH[4] = {a4.x, a4.y, a4.z, a4.w};
                uint32_t aL[4] = {b4.x, b4.y, b4.z, b4.w};
                mma_bf16(acc[0], aH, h4.x, h4.y);
                mma_bf16(acc[0], aH, l4.x, l4.y);
                mma_bf16(acc[0], aL, h4.x, h4.y);
                mma_bf16(acc[1], aH, h4.z, h4.w);
                mma_bf16(acc[1], aH, l4.z, l4.w);
                mma_bf16(acc[1], aL, h4.z, h4.w);
            }
            uint4* ih = (uint4*)(smem + OFF_INT);
            uint4 hv, lv;
            pack_epi(acc[0], acc[1], ss, tg, hv, lv);
            ih[(ss*4 + su)*32 + lane]        = hv;
            ih[1280 + (ss*4 + su)*32 + lane] = lv;
        }
        __syncthreads();

        int nxt = tile + gridDim.x;
        if (nxt < ntiles) stage(nxt);

        const uint4* ip = (const uint4*)(smem + OFF_INT);
        uint4* oh = (uint4*)outH;
        uint4* ol = (uint4*)outL;
#pragma unroll
        for (int sub = 0; sub < 4; sub++) {
            float acc[2][4] = {};
#pragma unroll
            for (int k0 = 0; k0 < KT; k0++) {
                uint4 a4 = ip[(k0*4 + sub)*32 + lane];
                uint4 b4 = ip[1280 + (k0*4 + sub)*32 + lane];
                uint32_t aH[4] = {a4.x, a4.y, a4.z, a4.w};
                uint32_t aL[4] = {b4.x, b4.y, b4.z, b4.w};
                mma_bf16(acc[0], aH, pbh[k0][0], pbh[k0][1]);
                mma_bf16(acc[0], aH, pbl[k0][0], pbl[k0][1]);
                mma_bf16(acc[0], aL, pbh[k0][0], pbh[k0][1]);
                mma_bf16(acc[1], aH, pbh[k0][2], pbh[k0][3]);
                mma_bf16(acc[1], aH, pbl[k0][2], pbl[k0][3]);
                mma_bf16(acc[1], aL, pbh[k0][2], pbh[k0][3]);
            }
            uint4 hv, lv;
            pack_epi(acc[0], acc[1], wid, tg, hv, lv);
            size_t base = ((size_t)tile * 40 + wid * 4 + sub) * 32 + lane;
            oh[base] = hv;
            ol[base] = lv;
        }
        {
            float acc[2][4] = {};
            const int scg = ss - 8;
#pragma unroll
            for (int k0 = 0; k0 < KT; k0++) {
                uint4 a4 = ip[(k0*4 + su)*32 + lane];
                uint4 b4 = ip[1280 + (k0*4 + su)*32 + lane];
                uint32_t aH[4] = {a4.x, a4.y, a4.z, a4.w};
                uint32_t aL[4] = {b4.x, b4.y, b4.z, b4.w};
                uint4 h4 = sb2[(scg*KT + k0)*32 + lane];
                uint4 l4 = sb2[640 + (scg*KT + k0)*32 + lane];
                mma_bf16(acc[0], aH, h4.x, h4.y);
                mma_bf16(acc[0], aH, l4.x, l4.y);
                mma_bf16(acc[0], aL, h4.x, h4.y);
                mma_bf16(acc[1], aH, h4.z, h4.w);
                mma_bf16(acc[1], aH, l4.z, l4.w);
                mma_bf16(acc[1], aL, h4.z, h4.w);
            }
            uint4 hv, lv;
            pack_epi(acc[0], acc[1], ss, tg, hv, lv);
            size_t base = ((size_t)tile * 40 + ss * 4 + su) * 32 + lane;
            oh[base] = hv;
            ol[base] = lv;
        }
        __syncthreads();
    }
}

// ===================== final layer + fused segment-sum (16 warps) ============
__global__ __launch_bounds__(512, 1)
void layer_atomic(const __nv_bfloat16* __restrict__ inH,
                  const __nv_bfloat16* __restrict__ inL,
                  const __nv_bfloat16* __restrict__ wimg,   // [160][72] hi,lo
                  const int* __restrict__ tgt,
                  float* __restrict__ ep,
                  int M)
{
    constexpr int THREADS = 512, KT = 10, WSTR = 72;
    constexpr int SLOT = 40960;

    extern __shared__ unsigned char smem[];
    const uint32_t sbu = smem_u32(smem);
    const int tid = threadIdx.x, wid = tid >> 5, lane = tid & 31;
    const int g = lane >> 2, tg = lane & 3;
    const int warp_n = wid & 3, sub = wid >> 2;

    uint32_t pbh[KT][4], pbl[KT][4];
    {
        const ushort* WH = (const ushort*)wimg;
        const ushort* WL = WH + 160 * WSTR;
#pragma unroll
        for (int k0 = 0; k0 < KT; k0++)
            wfrag(WH, WL, WSTR, k0, warp_n, g, tg, pbh[k0], pbl[k0]);
    }

    const int ntiles = (M + 63) >> 6;
    const uint4* hp = (const uint4*)inH;
    const uint4* lp = (const uint4*)inL;

    auto stage = [&](int slot, int tile) {
        if (tile < ntiles) {
            for (int i = tid; i < 2560; i += THREADS) {
                int plane = i / 1280, off = i - plane * 1280;
                const uint4* s = (plane ? lp : hp) + (size_t)tile * 1280 + off;
                cpa16(sbu + slot * SLOT + plane * 20480 + off * 16, s);
            }
        }
        CP_COMMIT();
    };

    int t0 = blockIdx.x;
    stage(0, t0);
    stage(1, t0 + gridDim.x);

    int i = 0;
    for (int t = t0; t < ntiles; t += gridDim.x, i++) {
        CP_WAIT1();
        __syncthreads();
        stage((i + 2) % 3, t + 2 * gridDim.x);

        const uint4* ap = (const uint4*)(smem + (i % 3) * SLOT);
        const size_t row0 = (size_t)t << 6;

        float acc[2][4] = {};
#pragma unroll
        for (int k0 = 0; k0 < KT; k0++) {
            uint4 a4 = ap[(k0*4 + sub)*32 + lane];
            uint4 b4 = ap[1280 + (k0*4 + sub)*32 + lane];
            uint32_t aH[4] = {a4.x, a4.y, a4.z, a4.w};
            uint32_t aL[4] = {b4.x, b4.y, b4.z, b4.w};
            mma_bf16(acc[0], aH, pbh[k0][0], pbh[k0][1]);
            mma_bf16(acc[0], aH, pbl[k0][0], pbl[k0][1]);
            mma_bf16(acc[0], aL, pbh[k0][0], pbh[k0][1]);
            mma_bf16(acc[1], aH, pbh[k0][2], pbh[k0][3]);
            mma_bf16(acc[1], aH, pbl[k0][2], pbl[k0][3]);
            mma_bf16(acc[1], aL, pbh[k0][2], pbh[k0][3]);
        }
        size_t gr0 = row0 + sub * 16 + g;
        size_t gr1 = gr0 + 8;
        int t0i = (gr0 < (size_t)M) ? __ldg(tgt + gr0) : -1;
        int t1i = (gr1 < (size_t)M) ? __ldg(tgt + gr1) : -1;
#pragma unroll
        for (int nh = 0; nh < 2; nh++) {
            int gc = warp_n * 16 + nh * 8 + tg * 2;
            if (gc < 50) {
                if (t0i >= 0) red2(ep + (size_t)t0i * 64 + gc, acc[nh][0], acc[nh][1]);
                if (t1i >= 0) red2(ep + (size_t)t1i * 64 + gc, acc[nh][2], acc[nh][3]);
            }
        }
    }
}

// ===================== SIMT GEMM (node MLP) =================================
template <int NS>
__global__ __launch_bounds__(256, 2)
void gemm_kernel(const float* __restrict__ A, int lda,
                 const float* __restrict__ W, const float* __restrict__ B,
                 float* __restrict__ C, int ldc,
                 int M, int din, int dout, int relu, int padstore)
{
    constexpr int PN = NS * 32;
    extern __shared__ float sm[];
    float* Ws = sm;
    float* Bs = Ws + ((din + 3) & ~3) * PN;
    const int tid = threadIdx.x;
    const int din4 = (din + 3) & ~3;
    for (int idx = tid; idx < din4 * PN; idx += 256) {
        int k = idx / PN, j = idx - k * PN;
        Ws[idx] = (k < din && j < dout) ? W[(size_t)k * dout + j] : 0.f;
    }
    for (int j = tid; j < PN; j += 256) Bs[j] = (j < dout) ? B[j] : 0.f;
    __syncthreads();
    const int lane = tid & 31;
    const int gwarp = blockIdx.x * 8 + (tid >> 5);
    const int nwarp = gridDim.x * 8;
    for (int sidx = gwarp; sidx < (M + 7) >> 3; sidx += nwarp) {
        const int row0 = sidx << 3;
        const float* ap[8];
#pragma unroll
        for (int r = 0; r < 8; r++) {
            int rr = row0 + r; if (rr > M - 1) rr = M - 1;
            ap[r] = A + (size_t)rr * lda;
        }
        float acc[8][NS];
#pragma unroll
        for (int r = 0; r < 8; r++)
#pragma unroll
            for (int s = 0; s < NS; s++) acc[r][s] = 0.f;
#pragma unroll 2
        for (int k = 0; k < din4; k += 4) {
            float4 a[8];
#pragma unroll
            for (int r = 0; r < 8; r++) a[r] = *(const float4*)(ap[r] + k);
#pragma unroll
            for (int kk = 0; kk < 4; kk++) {
                float wv[NS];
#pragma unroll
                for (int s = 0; s < NS; s++) wv[s] = Ws[(k + kk) * PN + lane + (s << 5)];
#pragma unroll
                for (int r = 0; r < 8; r++) {
                    float av = (kk == 0) ? a[r].x : (kk == 1) ? a[r].y : (kk == 2) ? a[r].z : a[r].w;
#pragma unroll
                    for (int s = 0; s < NS; s++) acc[r][s] = fmaf(av, wv[s], acc[r][s]);
                }
            }
        }
#pragma unroll
        for (int r = 0; r < 8; r++) {
            int row = row0 + r;
            if (row < M) {
#pragma unroll
                for (int s = 0; s < NS; s++) {
                    int j = lane + (s << 5);
                    float v = acc[r][s] + Bs[j];
                    if (relu) v = fmaxf(v, 0.f);
                    if (padstore || j < dout) C[(size_t)row * ldc + j] = v;
                }
            }
        }
    }
}

// ===================== host ==================================================
static inline size_t smbytes(int din, int PN)
{
    int din4 = (din + 3) & ~3;
    return (size_t)(din4 * PN + PN) * sizeof(float);
}

extern "C" void kernel_launch(void* const* d_in, const int* in_sizes, int n_in,
                              void* d_out, int out_size)
{
    const float* t   = (const float*)d_in[0];
    const float* x   = (const float*)d_in[1];
    const float* ofx = (const float*)d_in[2];
    const int* src   = (const int*)d_in[3];
    const int* tgt   = (const int*)d_in[4];
    const float* RW[5] = {(const float*)d_in[5], (const float*)d_in[7], (const float*)d_in[9],
                          (const float*)d_in[11], (const float*)d_in[13]};
    const float* Rb[5] = {(const float*)d_in[6], (const float*)d_in[8], (const float*)d_in[10],
                          (const float*)d_in[12], (const float*)d_in[14]};
    const float* OW0 = (const float*)d_in[15];
    const float* Ob0 = (const float*)d_in[16];
    const float* OW1 = (const float*)d_in[17];
    const float* Ob1 = (const float*)d_in[18];
    float* out = (float*)d_out;

    const int M = in_sizes[3];
    const int N = in_sizes[1] / 4;

    __nv_bfloat16 *rpH, *rpL, *Xh, *Xl, *Yh, *Yl, *wst;
    float* ep;
    cudaGetSymbolAddress((void**)&rpH, g_rpH);
    cudaGetSymbolAddress((void**)&rpL, g_rpL);
    cudaGetSymbolAddress((void**)&Xh,  g_Xh);
    cudaGetSymbolAddress((void**)&Xl,  g_Xl);
    cudaGetSymbolAddress((void**)&Yh,  g_Yh);
    cudaGetSymbolAddress((void**)&Yl,  g_Yl);
    cudaGetSymbolAddress((void**)&ep,  g_eprime);
    cudaGetSymbolAddress((void**)&wst, g_wstage);

    int nsm = 148;
    cudaDeviceGetAttribute(&nsm, cudaDevAttrMultiProcessorCount, 0);

    const int woff[5] = {0, 5376, 59136, 112896, 166656};
    const int wdin[5]  = {13, 150, 150, 150, 150};
    const int wdout[5] = {150, 150, 150, 150, 50};
    const int wKD[5]   = {16, 160, 160, 160, 160};
    const int wWSTR[5] = {168, 168, 168, 168, 72};
    const int wbrow[5] = {13, 150, 150, 150, 150};
    PrepPack pk;
    int ptotal = 0;
    for (int i = 0; i < 5; i++) {
        pk.c[i] = PrepCfg{RW[i], Rb[i], wdin[i], wdout[i], wKD[i], wWSTR[i], wbrow[i], woff[i]};
        ptotal += wKD[i] * wWSTR[i];
    }
    prep_all<<<(ptotal + 255) / 256, 256>>>(pk, wst, ptotal);

    zero_kernel<<<(N * 64 + 255) / 256, 256>>>(ep, N * 64);
    gather_kernel<<<(M + 255) / 256, 256>>>(x, ofx, src, tgt, t, rpH, rpL, M);

    const int sm01 = 81920 + 51200 + 10240;                 // 143360
    const int sm23 = 2*51200 + 20480 + 40960 + 40960;       // 204800
    const int sm4  = 3 * 40960;                             // 122880
    cudaFuncSetAttribute(pair1_kernel, cudaFuncAttributeMaxDynamicSharedMemorySize, sm01);
    cudaFuncSetAttribute(pair2_kernel, cudaFuncAttributeMaxDynamicSharedMemorySize, sm23);
    cudaFuncSetAttribute(layer_atomic, cudaFuncAttributeMaxDynamicSharedMemorySize, sm4);

    pair1_kernel<<<nsm, 256, sm01>>>(rpH, rpL, wst + woff[0], wst + woff[1], Xh, Xl, M);
    pair2_kernel<<<nsm, 256, sm23>>>(Xh, Xl, wst + woff[2], wst + woff[3], Yh, Yl, M);
    layer_atomic<<<nsm, 512, sm4>>>(Yh, Yl, wst + woff[4], tgt, ep, M);

    cudaFuncSetAttribute(gemm_kernel<4>, cudaFuncAttributeMaxDynamicSharedMemorySize, 112 * 1024);
    cudaFuncSetAttribute(gemm_kernel<1>, cudaFuncAttributeMaxDynamicSharedMemorySize, 112 * 1024);
    float* nb = (float*)rpH;
    gemm_kernel<4><<<2 * nsm, 256, smbytes(50, 128)>>>(ep, 64, OW0, Ob0, nb, 128, N, 50, 100, 1, 1);
    gemm_kernel<1><<<2 * nsm, 256, smbytes(100, 32)>>>(nb, 128, OW1, Ob1, out, 4, N, 100, 4, 0, 0);
}